// round 4
// baseline (speedup 1.0000x reference)
#include <cuda_runtime.h>
#include <cstdint>
#include <math.h>

#define Bq   4
#define Nq   4096
#define Cq   256
#define DKq  64
#define NROWS (Bq*Nq)          // 16384
#define KC   192               // concatenated split-K
#define NEG_BIG (-3.402823466e38f)

// split-TF32 concatenated operands:
//  g_Qc[m][0:64]=hi [64:128]=hi [128:192]=lo
//  g_Kc[n][0:64]=hi [64:128]=lo [128:192]=hi
__device__ float g_Qc[NROWS*KC];
__device__ float g_Kc[NROWS*KC];

__device__ __forceinline__ void fma2(unsigned long long &acc,
                                     unsigned long long a, unsigned long long b) {
    asm volatile("fma.rn.f32x2 %0, %1, %2, %0;" : "+l"(acc) : "l"(a), "l"(b));
}
__device__ __forceinline__ float tf32_rna(float v) {
    uint32_t b;
    asm("cvt.rna.tf32.f32 %0, %1;" : "=r"(b) : "f"(v));
    return __uint_as_float(b);
}
__device__ __forceinline__ uint32_t smem_u32(const void* p) {
    uint32_t a;
    asm("{ .reg .u64 t; cvta.to.shared.u64 t, %1; cvt.u32.u64 %0, t; }" : "=r"(a) : "l"(p));
    return a;
}
__device__ __forceinline__ void cpa16(uint32_t dst, const void* src) {
    asm volatile("cp.async.cg.shared.global [%0], [%1], 16;" :: "r"(dst), "l"(src));
}

// =====================================================================
// Kernel 1: projections  Q = x @ Wq,  K = x @ Wk  (+ tf32 hi/lo split emit)
// (unchanged from R1 — exact fp32, ~50us)
// =====================================================================
#define XP 36

__global__ __launch_bounds__(256) void proj_kernel(
        const float* __restrict__ x,
        const float* __restrict__ Wq,
        const float* __restrict__ Wk) {
    __shared__ float Xs[64*XP];
    __shared__ float Ws[128*XP];
    int t  = threadIdx.x;
    int rb = blockIdx.x;
    int b  = rb >> 6;
    int n0 = (rb & 63) << 6;
    int tx = t & 15, ty = t >> 4;

    unsigned long long acc[4][8];
#pragma unroll
    for (int i = 0; i < 4; i++)
#pragma unroll
        for (int j = 0; j < 8; j++) acc[i][j] = 0ull;

    const float* xb = x + (size_t)(b*Nq + n0) * Cq;

    for (int c0 = 0; c0 < Cq; c0 += 32) {
#pragma unroll
        for (int s = 0; s < 2; s++) {
            int li = t + s*256;
            int r = li >> 3, cq = li & 7;
            float4 v = *(const float4*)(xb + (size_t)r*Cq + c0 + cq*4);
            *(float4*)(&Xs[r*XP + cq*4]) = v;
        }
#pragma unroll
        for (int s = 0; s < 16; s++) {
            int li  = t + s*256;
            int mat = li >> 11;
            int rem = li & 2047;
            int cc  = rem >> 6;
            int jj  = rem & 63;
            const float* W = mat ? Wk : Wq;
            Ws[(mat*64 + jj)*XP + cc] = W[(size_t)(c0+cc)*DKq + jj];
        }
        __syncthreads();
#pragma unroll
        for (int cc = 0; cc < 32; cc += 4) {
            ulonglong2 qv[4];
#pragma unroll
            for (int i = 0; i < 4; i++)
                qv[i] = *(const ulonglong2*)(&Xs[(ty + 16*i)*XP + cc]);
#pragma unroll
            for (int j = 0; j < 8; j++) {
                ulonglong2 wv = *(const ulonglong2*)(&Ws[(tx + 16*j)*XP + cc]);
#pragma unroll
                for (int i = 0; i < 4; i++) {
                    fma2(acc[i][j], qv[i].x, wv.x);
                    fma2(acc[i][j], qv[i].y, wv.y);
                }
            }
        }
        __syncthreads();
    }
#pragma unroll
    for (int i = 0; i < 4; i++) {
        size_t m = (size_t)rb*64 + ty + 16*i;
#pragma unroll
        for (int j = 0; j < 8; j++) {
            int col = tx + 16*j;
            union { unsigned long long u; float2 f; } cv; cv.u = acc[i][j];
            float v  = cv.f.x + cv.f.y;
            float hi = tf32_rna(v);
            float lo = tf32_rna(v - hi);
            if (col < 64) {                       // Q: [hi | hi | lo]
                g_Qc[m*KC + col]       = hi;
                g_Qc[m*KC + 64 + col]  = hi;
                g_Qc[m*KC + 128 + col] = lo;
            } else {                              // K: [hi | lo | hi]
                int k = col - 64;
                g_Kc[m*KC + k]         = hi;
                g_Kc[m*KC + 64 + k]    = lo;
                g_Kc[m*KC + 128 + k]   = hi;
            }
        }
    }
}

// =====================================================================
// Kernel 2: warp-level tf32 mma.sync GEMM (K=192 split) + fused top-8
//   CTA: 128 threads (4 warps), 128 query rows. 64 key tiles of 64.
//   Warp tile: 32(M) x 64(N); 2 m16 x 8 n8 x 24 k8 = 384 mma/warp/tile.
//   Smem pitch 196 floats -> conflict-free fragment LDS.
// =====================================================================
#define QP     196                      // floats
#define QPB    (QP*4)                   // 784 bytes
#define OFF_Q  0
#define QBYTES (128*QPB)                // 100352
#define OFF_B0 QBYTES
#define BBYTES (64*QPB)                 // 50176
#define OFF_B1 (OFF_B0 + BBYTES)
#define SMEM_EDGE (OFF_B1 + BBYTES)     // 200704

__device__ __forceinline__ void mma8(float c[4], uint32_t a0, uint32_t a1,
                                     uint32_t a2, uint32_t a3,
                                     uint32_t b0, uint32_t b1) {
    asm volatile(
        "mma.sync.aligned.m16n8k8.row.col.f32.tf32.tf32.f32 "
        "{%0,%1,%2,%3},{%4,%5,%6,%7},{%8,%9},{%0,%1,%2,%3};"
        : "+f"(c[0]), "+f"(c[1]), "+f"(c[2]), "+f"(c[3])
        : "r"(a0), "r"(a1), "r"(a2), "r"(a3), "r"(b0), "r"(b1));
}

__device__ __forceinline__ void ins8(float* vals, int* idx, float v, int ci) {
    if (v > vals[7]) {
        float cv = v;
#pragma unroll
        for (int q = 0; q < 8; q++) {
            if (cv > vals[q]) {
                float tv = vals[q]; int ti = idx[q];
                vals[q] = cv; idx[q] = ci; cv = tv; ci = ti;
            }
        }
    }
}

__global__ __launch_bounds__(128)
void edge_kernel(float* __restrict__ out) {
    extern __shared__ __align__(16) char smem[];
    uint32_t sb = smem_u32(smem);
    const uint32_t* Qu = (const uint32_t*)(smem + OFF_Q);

    int tid = threadIdx.x;
    int wid = tid >> 5, lane = tid & 31;
    int g = lane >> 2, tg = lane & 3;       // fragment row-group / in-group

    int m0    = blockIdx.x * 128;
    int batch = blockIdx.x >> 5;            // 32 CTAs per batch

    // ---- load Q tile (128 x 192) ----
    const float* qsrc = g_Qc + (size_t)m0 * KC;
#pragma unroll
    for (int i = 0; i < 48; i++) {
        int idx = tid + i*128;              // 0..6143
        int r = idx / 48, c = idx % 48;
        cpa16(sb + OFF_Q + (uint32_t)(r*QPB + c*16), qsrc + (size_t)r*KC + c*4);
    }
    const float* gK = g_Kc + (size_t)batch * Nq * KC;
    // prefetch K tile 0
#pragma unroll
    for (int i = 0; i < 24; i++) {
        int idx = tid + i*128;              // 0..3071
        int r = idx / 48, c = idx % 48;
        cpa16(sb + OFF_B0 + (uint32_t)(r*QPB + c*16), gK + (size_t)r*KC + c*4);
    }
    asm volatile("cp.async.commit_group;");

    float vals[4][8]; int idx8[4][8];
#pragma unroll
    for (int l = 0; l < 4; l++)
#pragma unroll
        for (int q = 0; q < 8; q++) { vals[l][q] = NEG_BIG; idx8[l][q] = 0; }

    float4* out4 = (float4*)out;
    size_t ob4 = (size_t)m0 * (Nq/4);
    const float4 z4 = make_float4(0.f, 0.f, 0.f, 0.f);

    for (int kt = 0; kt < 64; kt++) {
        const uint32_t* Bu = (const uint32_t*)(smem + ((kt & 1) ? OFF_B1 : OFF_B0));
        // prefetch next K tile into the other buffer
        if (kt < 63) {
            uint32_t boff = (kt & 1) ? OFF_B0 : OFF_B1;
            const float* src = gK + (size_t)(kt + 1)*64*KC;
#pragma unroll
            for (int i = 0; i < 24; i++) {
                int idx = tid + i*128;
                int r = idx / 48, c = idx % 48;
                cpa16(sb + boff + (uint32_t)(r*QPB + c*16), src + (size_t)r*KC + c*4);
            }
            asm volatile("cp.async.commit_group;");
            asm volatile("cp.async.wait_group 1;");
        } else {
            asm volatile("cp.async.wait_group 0;");
        }
        __syncthreads();

        // ---- streaming zero-fill of output slice (hidden under MMA) ----
#pragma unroll
        for (int s = 0; s < 16; s++)
            __stcs(&out4[ob4 + (size_t)kt*2048 + tid + s*128], z4);

        // ---- warp-level tf32 GEMM: 32x64 subtile over K=192 ----
        float c[2][8][4];
#pragma unroll
        for (int m = 0; m < 2; m++)
#pragma unroll
            for (int j = 0; j < 8; j++)
#pragma unroll
                for (int q = 0; q < 4; q++) c[m][j][q] = 0.f;

#pragma unroll
        for (int ks = 0; ks < 24; ks++) {
            int k0 = ks * 8;
            uint32_t a[2][4];
#pragma unroll
            for (int m = 0; m < 2; m++) {
                int rb = wid*32 + m*16 + g;
                a[m][0] = Qu[rb*QP + k0 + tg];
                a[m][1] = Qu[(rb + 8)*QP + k0 + tg];
                a[m][2] = Qu[rb*QP + k0 + 4 + tg];
                a[m][3] = Qu[(rb + 8)*QP + k0 + 4 + tg];
            }
#pragma unroll
            for (int j = 0; j < 8; j++) {
                int n = j*8 + g;
                uint32_t b0 = Bu[n*QP + k0 + tg];
                uint32_t b1 = Bu[n*QP + k0 + 4 + tg];
#pragma unroll
                for (int m = 0; m < 2; m++)
                    mma8(c[m][j], a[m][0], a[m][1], a[m][2], a[m][3], b0, b1);
            }
        }

        // ---- top-8 scan of this tile's C fragments ----
#pragma unroll
        for (int m = 0; m < 2; m++) {
#pragma unroll
            for (int j = 0; j < 8; j++) {
                int c0 = kt*64 + j*8 + 2*tg;
                ins8(vals[2*m],     idx8[2*m],     c[m][j][0], c0);
                ins8(vals[2*m],     idx8[2*m],     c[m][j][1], c0 + 1);
                ins8(vals[2*m + 1], idx8[2*m + 1], c[m][j][2], c0);
                ins8(vals[2*m + 1], idx8[2*m + 1], c[m][j][3], c0 + 1);
            }
        }
        __syncthreads();
    }

    // ---- merge 4 partial lists per row via smem (Q region is dead now) ----
    float* MV = (float*)smem;                    // [128][33]
    int*   MI = (int*)(smem + 128*33*4);         // [128][33]
#pragma unroll
    for (int l = 0; l < 4; l++) {
        int m = l >> 1, h = l & 1;
        int row = wid*32 + m*16 + h*8 + g;       // warp-local row 0..31 -> CTA row
        int part = tg;
#pragma unroll
        for (int q = 0; q < 8; q++) {
            MV[row*33 + part*8 + q] = vals[l][q];
            MI[row*33 + part*8 + q] = idx8[l][q];
        }
    }
    __syncthreads();

    // ---- per-row final top-8 + softmax + sparse scatter ----
    {
        int row = tid;                           // 0..127
        float bv[8]; int bi[8];
#pragma unroll
        for (int sel = 0; sel < 8; sel++) {
            float best = NEG_BIG; int bidx = 0, bslot = 0;
            for (int q = 0; q < 32; q++) {
                float v = MV[row*33 + q];
                if (v > best) { best = v; bidx = MI[row*33 + q]; bslot = q; }
            }
            bv[sel] = best; bi[sel] = bidx;
            MV[row*33 + bslot] = NEG_BIG;
        }
        float mx = bv[0];
        float e[8], Z = 0.f;
#pragma unroll
        for (int q = 0; q < 8; q++) { e[q] = expf(0.125f*(bv[q] - mx)); Z += e[q]; }
        float inv = 1.0f / Z;
        size_t ro = (size_t)(m0 + row) * Nq;
#pragma unroll
        for (int q = 0; q < 8; q++) out[ro + bi[q]] = e[q] * inv;
    }
}

// =====================================================================
extern "C" void kernel_launch(void* const* d_in, const int* in_sizes, int n_in,
                              void* d_out, int out_size) {
    const float* x  = (const float*)d_in[0];
    const float* Wq = (const float*)d_in[1];
    const float* Wk = (const float*)d_in[2];
    float* out = (float*)d_out;

    cudaFuncSetAttribute(edge_kernel,
                         cudaFuncAttributeMaxDynamicSharedMemorySize, SMEM_EDGE);

    proj_kernel<<<NROWS/64, 256>>>(x, Wq, Wk);
    edge_kernel<<<NROWS/128, 128, SMEM_EDGE>>>(out);
}

// round 6
// speedup vs baseline: 1.3191x; 1.3191x over previous
#include <cuda_runtime.h>
#include <cstdint>
#include <math.h>

#define Bq   4
#define Nq   4096
#define Cq   256
#define DKq  64
#define NROWS (Bq*Nq)          // 16384
#define NEG_BIG (-3.402823466e38f)

// proj outputs: exact fp32 (for rescore) + tf32-hi (for approx GEMM)
__device__ float g_Qf[NROWS*DKq];
__device__ float g_Kf[NROWS*DKq];
__device__ float g_Qh[NROWS*DKq];
__device__ float g_Kh[NROWS*DKq];
__device__ int   g_cand[NROWS*64];      // 64 candidate cols per row

__device__ __forceinline__ void fma2(unsigned long long &acc,
                                     unsigned long long a, unsigned long long b) {
    asm volatile("fma.rn.f32x2 %0, %1, %2, %0;" : "+l"(acc) : "l"(a), "l"(b));
}
__device__ __forceinline__ float tf32_rna(float v) {
    uint32_t b;
    asm("cvt.rna.tf32.f32 %0, %1;" : "=r"(b) : "f"(v));
    return __uint_as_float(b);
}
__device__ __forceinline__ uint32_t smem_u32(const void* p) {
    uint32_t a;
    asm("{ .reg .u64 t; cvta.to.shared.u64 t, %1; cvt.u32.u64 %0, t; }" : "=r"(a) : "l"(p));
    return a;
}
__device__ __forceinline__ void cpa16(uint32_t dst, const void* src) {
    asm volatile("cp.async.cg.shared.global [%0], [%1], 16;" :: "r"(dst), "l"(src));
}

// =====================================================================
// Kernel 1: projections (exact fp32) + tf32-hi emit
// =====================================================================
#define XP 36

__global__ __launch_bounds__(256) void proj_kernel(
        const float* __restrict__ x,
        const float* __restrict__ Wq,
        const float* __restrict__ Wk) {
    __shared__ float Xs[64*XP];
    __shared__ float Ws[128*XP];
    int t  = threadIdx.x;
    int rb = blockIdx.x;
    int b  = rb >> 6;
    int n0 = (rb & 63) << 6;
    int tx = t & 15, ty = t >> 4;

    unsigned long long acc[4][8];
#pragma unroll
    for (int i = 0; i < 4; i++)
#pragma unroll
        for (int j = 0; j < 8; j++) acc[i][j] = 0ull;

    const float* xb = x + (size_t)(b*Nq + n0) * Cq;

    for (int c0 = 0; c0 < Cq; c0 += 32) {
#pragma unroll
        for (int s = 0; s < 2; s++) {
            int li = t + s*256;
            int r = li >> 3, cq = li & 7;
            float4 v = *(const float4*)(xb + (size_t)r*Cq + c0 + cq*4);
            *(float4*)(&Xs[r*XP + cq*4]) = v;
        }
#pragma unroll
        for (int s = 0; s < 16; s++) {
            int li  = t + s*256;
            int mat = li >> 11;
            int rem = li & 2047;
            int cc  = rem >> 6;
            int jj  = rem & 63;
            const float* W = mat ? Wk : Wq;
            Ws[(mat*64 + jj)*XP + cc] = W[(size_t)(c0+cc)*DKq + jj];
        }
        __syncthreads();
#pragma unroll
        for (int cc = 0; cc < 32; cc += 4) {
            ulonglong2 qv[4];
#pragma unroll
            for (int i = 0; i < 4; i++)
                qv[i] = *(const ulonglong2*)(&Xs[(ty + 16*i)*XP + cc]);
#pragma unroll
            for (int j = 0; j < 8; j++) {
                ulonglong2 wv = *(const ulonglong2*)(&Ws[(tx + 16*j)*XP + cc]);
#pragma unroll
                for (int i = 0; i < 4; i++) {
                    fma2(acc[i][j], qv[i].x, wv.x);
                    fma2(acc[i][j], qv[i].y, wv.y);
                }
            }
        }
        __syncthreads();
    }
#pragma unroll
    for (int i = 0; i < 4; i++) {
        size_t m = (size_t)rb*64 + ty + 16*i;
#pragma unroll
        for (int j = 0; j < 8; j++) {
            int col = tx + 16*j;
            union { unsigned long long u; float2 f; } cv; cv.u = acc[i][j];
            float v  = cv.f.x + cv.f.y;
            if (col < 64) {
                g_Qf[m*DKq + col] = v;
                g_Qh[m*DKq + col] = tf32_rna(v);
            } else {
                int k = col - 64;
                g_Kf[m*DKq + k] = v;
                g_Kh[m*DKq + k] = tf32_rna(v);
            }
        }
    }
}

// =====================================================================
// Kernel 2: approx GEMM (tf32 hi only, K=64) + per-part top-8 candidates
//   grid 256: (row-block of 128) x (key-half of 2048). 4 warps, 32x64 tiles.
// =====================================================================
#define QP     68
#define QPB    (QP*4)                   // 272 bytes
#define OFF_Q  0
#define QBYTES (128*QPB)                // 34816
#define OFF_B0 QBYTES
#define BBYTES (64*QPB)                 // 17408
#define OFF_B1 (OFF_B0 + BBYTES)
#define SMEM_EDGE (OFF_B1 + BBYTES)     // 69632

__device__ __forceinline__ void mma8(float c[4], uint32_t a0, uint32_t a1,
                                     uint32_t a2, uint32_t a3,
                                     uint32_t b0, uint32_t b1) {
    asm volatile(
        "mma.sync.aligned.m16n8k8.row.col.f32.tf32.tf32.f32 "
        "{%0,%1,%2,%3},{%4,%5,%6,%7},{%8,%9},{%0,%1,%2,%3};"
        : "+f"(c[0]), "+f"(c[1]), "+f"(c[2]), "+f"(c[3])
        : "r"(a0), "r"(a1), "r"(a2), "r"(a3), "r"(b0), "r"(b1));
}

__device__ __forceinline__ void ins8(float* vals, int* idx, float v, int ci) {
    if (v > vals[7]) {
        float cv = v;
#pragma unroll
        for (int q = 0; q < 8; q++) {
            if (cv > vals[q]) {
                float tv = vals[q]; int ti = idx[q];
                vals[q] = cv; idx[q] = ci; cv = tv; ci = ti;
            }
        }
    }
}

__global__ __launch_bounds__(128, 2)
void edge_kernel(float* __restrict__ out) {
    extern __shared__ __align__(16) char smem[];
    uint32_t sb = smem_u32(smem);
    const uint32_t* Qu = (const uint32_t*)(smem + OFF_Q);

    int tid = threadIdx.x;
    int wid = tid >> 5, lane = tid & 31;
    int g = lane >> 2, tg = lane & 3;

    int bid  = blockIdx.x;
    int rb   = bid >> 1;
    int half = bid & 1;
    int m0    = rb * 128;
    int batch = rb >> 5;
    int kt0   = half * 32;

    // ---- load Q-hi tile (128 x 64) ----
    const float* qsrc = g_Qh + (size_t)m0 * DKq;
#pragma unroll
    for (int i = 0; i < 16; i++) {
        int idx = tid + i*128;              // 0..2047 float4s
        int r = idx >> 4, c = idx & 15;
        cpa16(sb + OFF_Q + (uint32_t)(r*QPB + c*16), qsrc + (size_t)r*DKq + c*4);
    }
    const float* gK = g_Kh + (size_t)batch * Nq * DKq;
    // prefetch key tile 0 of this half
    {
        const float* src = gK + (size_t)kt0*64*DKq;
#pragma unroll
        for (int i = 0; i < 8; i++) {
            int idx = tid + i*128;          // 0..1023 float4s
            int r = idx >> 4, c = idx & 15;
            cpa16(sb + OFF_B0 + (uint32_t)(r*QPB + c*16), src + (size_t)r*DKq + c*4);
        }
    }
    asm volatile("cp.async.commit_group;");

    float vals[4][8]; int idx8[4][8];
#pragma unroll
    for (int l = 0; l < 4; l++)
#pragma unroll
        for (int q = 0; q < 8; q++) { vals[l][q] = NEG_BIG; idx8[l][q] = 0; }

    float4* out4 = (float4*)out;
    const float4 z4 = make_float4(0.f, 0.f, 0.f, 0.f);

    for (int ktl = 0; ktl < 32; ktl++) {
        int kt = kt0 + ktl;
        const uint32_t* Bu = (const uint32_t*)(smem + ((ktl & 1) ? OFF_B1 : OFF_B0));
        if (ktl < 31) {
            uint32_t boff = (ktl & 1) ? OFF_B0 : OFF_B1;
            const float* src = gK + (size_t)(kt + 1)*64*DKq;
#pragma unroll
            for (int i = 0; i < 8; i++) {
                int idx = tid + i*128;
                int r = idx >> 4, c = idx & 15;
                cpa16(sb + boff + (uint32_t)(r*QPB + c*16), src + (size_t)r*DKq + c*4);
            }
            asm volatile("cp.async.commit_group;");
            asm volatile("cp.async.wait_group 1;");
        } else {
            asm volatile("cp.async.wait_group 0;");
        }
        __syncthreads();

        // ---- streaming zero-fill of this tile's output columns ----
#pragma unroll
        for (int s = 0; s < 16; s++) {
            int idx = tid + s*128;          // 0..2047
            int r = idx >> 4, c = idx & 15;
            __stcs(&out4[(size_t)(m0 + r)*1024 + kt*16 + c], z4);
        }

        // ---- warp tf32 GEMM: 32x64 subtile, K=64 ----
        float c[2][8][4];
#pragma unroll
        for (int m = 0; m < 2; m++)
#pragma unroll
            for (int j = 0; j < 8; j++)
#pragma unroll
                for (int q = 0; q < 4; q++) c[m][j][q] = 0.f;

#pragma unroll
        for (int ks = 0; ks < 8; ks++) {
            int k0 = ks * 8;
            uint32_t a[2][4];
#pragma unroll
            for (int m = 0; m < 2; m++) {
                int rr = wid*32 + m*16 + g;
                a[m][0] = Qu[rr*QP + k0 + tg];
                a[m][1] = Qu[(rr + 8)*QP + k0 + tg];
                a[m][2] = Qu[rr*QP + k0 + 4 + tg];
                a[m][3] = Qu[(rr + 8)*QP + k0 + 4 + tg];
            }
#pragma unroll
            for (int j = 0; j < 8; j++) {
                int n = j*8 + g;
                uint32_t b0 = Bu[n*QP + k0 + tg];
                uint32_t b1 = Bu[n*QP + k0 + 4 + tg];
#pragma unroll
                for (int m = 0; m < 2; m++)
                    mma8(c[m][j], a[m][0], a[m][1], a[m][2], a[m][3], b0, b1);
            }
        }

        // ---- per-part top-8 scan ----
#pragma unroll
        for (int m = 0; m < 2; m++) {
#pragma unroll
            for (int j = 0; j < 8; j++) {
                int c0 = kt*64 + j*8 + 2*tg;
                ins8(vals[2*m],     idx8[2*m],     c[m][j][0], c0);
                ins8(vals[2*m],     idx8[2*m],     c[m][j][1], c0 + 1);
                ins8(vals[2*m + 1], idx8[2*m + 1], c[m][j][2], c0);
                ins8(vals[2*m + 1], idx8[2*m + 1], c[m][j][3], c0 + 1);
            }
        }
        __syncthreads();
    }

    // ---- dump candidate indices (no merge, no softmax) ----
#pragma unroll
    for (int l = 0; l < 4; l++) {
        int rl = wid*32 + (l >> 1)*16 + (l & 1)*8 + g;
        size_t base = (size_t)(m0 + rl)*64 + half*32 + tg*8;
#pragma unroll
        for (int q = 0; q < 8; q++) g_cand[base + q] = idx8[l][q];
    }
}

// =====================================================================
// Kernel 3: exact fp32 rescore of 64 candidates/row + top-8 + softmax
//   256 threads = 8 warps, 1 warp per row, grid = NROWS/8.
// =====================================================================
__global__ __launch_bounds__(256) void rescore_kernel(float* __restrict__ out) {
    __shared__ float qs[8*64];
    int tid = threadIdx.x;
    int w = tid >> 5, lane = tid & 31;
    int row   = blockIdx.x*8 + w;
    int batch = row >> 12;

    qs[w*64 + lane]      = g_Qf[(size_t)row*DKq + lane];
    qs[w*64 + 32 + lane] = g_Qf[(size_t)row*DKq + 32 + lane];
    __syncwarp();

    const float* Kf = g_Kf + (size_t)batch * Nq * DKq;
    const float4* qr = (const float4*)(qs + w*64);

    float s0, s1; int i0, i1;
#pragma unroll
    for (int h = 0; h < 2; h++) {
        int ci = g_cand[(size_t)row*64 + h*32 + lane];
        const float4* kr = (const float4*)(Kf + (size_t)ci*DKq);
        float acc = 0.f;
#pragma unroll
        for (int d = 0; d < 16; d++) {
            float4 kv = kr[d];
            float4 qv = qr[d];
            acc += qv.x*kv.x + qv.y*kv.y + qv.z*kv.z + qv.w*kv.w;
        }
        if (h == 0) { s0 = acc; i0 = ci; } else { s1 = acc; i1 = ci; }
    }

    // warp-parallel top-8 of 64 (each lane holds 2), lower index wins ties
    float bv[8]; int bi[8];
#pragma unroll
    for (int sel = 0; sel < 8; sel++) {
        float v; int ix;
        if (s0 > s1 || (s0 == s1 && i0 < i1)) { v = s0; ix = i0; }
        else                                  { v = s1; ix = i1; }
#pragma unroll
        for (int off = 16; off > 0; off >>= 1) {
            float vv = __shfl_xor_sync(0xFFFFFFFFu, v, off);
            int   ii = __shfl_xor_sync(0xFFFFFFFFu, ix, off);
            if (vv > v || (vv == v && ii < ix)) { v = vv; ix = ii; }
        }
        bv[sel] = v; bi[sel] = ix;
        if (i0 == ix) s0 = NEG_BIG;
        if (i1 == ix) s1 = NEG_BIG;
    }

    // softmax over 8 (all lanes have identical bv/bi); lanes 0-7 scatter
    float mx = bv[0];
    float Z = 0.f, e[8];
#pragma unroll
    for (int q = 0; q < 8; q++) { e[q] = expf(0.125f*(bv[q] - mx)); Z += e[q]; }
    float inv = 1.0f / Z;
    if (lane < 8)
        out[(size_t)row*Nq + bi[lane]] = e[lane] * inv;
}

// =====================================================================
extern "C" void kernel_launch(void* const* d_in, const int* in_sizes, int n_in,
                              void* d_out, int out_size) {
    const float* x  = (const float*)d_in[0];
    const float* Wq = (const float*)d_in[1];
    const float* Wk = (const float*)d_in[2];
    float* out = (float*)d_out;

    cudaFuncSetAttribute(edge_kernel,
                         cudaFuncAttributeMaxDynamicSharedMemorySize, SMEM_EDGE);

    proj_kernel<<<NROWS/64, 256>>>(x, Wq, Wk);
    edge_kernel<<<NROWS/64, 128, SMEM_EDGE>>>(out);   // 256 CTAs (128 rows x 2 halves)
    rescore_kernel<<<NROWS/8, 256>>>(out);
}